// round 17
// baseline (speedup 1.0000x reference)
#include <cuda_runtime.h>

#define Hh 51
#define NB 4
#define NTH 448
#define BTOT 512
#define RSTR 56                         // floats per h row (52 used, padded)
#define SLOT_B (NB * RSTR * 4)          // 896 B per ring slot
#define H2OFF (2 * SLOT_B)              // h2 ring offset from h1 ring base

// named barrier ids
#define BFREE0 1
#define BFREE1 2
#define BFULL0 3
#define BFULL1 4
#define BXB    5
#define BABAR  6
#define SYNC448(id)   asm volatile("bar.sync %0, 448;"   :: "n"(id))
#define ARRIVE448(id) asm volatile("bar.arrive %0, 448;" :: "n"(id))
#define SYNCA()       asm volatile("bar.sync %0, 224;"   :: "n"(BABAR))

__device__ __forceinline__ unsigned long long pack2(float lo, float hi) {
    unsigned long long r;
    asm("mov.b64 %0, {%1,%2};" : "=l"(r) : "f"(lo), "f"(hi));
    return r;
}
__device__ __forceinline__ void ffma2(unsigned long long &acc, unsigned long long a, unsigned long long b) {
    asm("fma.rn.f32x2 %0, %1, %2, %0;" : "+l"(acc) : "l"(a), "l"(b));
}
__device__ __forceinline__ float sum2(unsigned long long a) {
    float lo, hi;
    asm("mov.b64 {%0,%1}, %2;" : "=f"(lo), "=f"(hi) : "l"(a));
    return lo + hi;
}
__device__ __forceinline__ void lds128(unsigned long long &p0, unsigned long long &p1, unsigned addr) {
    asm volatile("ld.shared.v2.b64 {%0,%1}, [%2];" : "=l"(p0), "=l"(p1) : "r"(addr));
}
__device__ __forceinline__ float ftanh_(float x) {
    float r;
    asm("tanh.approx.f32 %0, %1;" : "=f"(r) : "f"(x));
    return r;
}

// 4x4 transpose across lane bits 3..4 (gate <-> batch-slot).
__device__ __forceinline__ void transp4(float v[4], int lane) {
    {
        bool lo = lane & 8;
        float tA = lo ? v[0] : v[1];
        float tB = lo ? v[2] : v[3];
        tA = __shfl_xor_sync(0xffffffffu, tA, 8);
        tB = __shfl_xor_sync(0xffffffffu, tB, 8);
        if (lo) { v[0] = tA; v[2] = tB; } else { v[1] = tA; v[3] = tB; }
    }
    {
        bool hi = lane & 16;
        float uA = hi ? v[0] : v[2];
        float uB = hi ? v[1] : v[3];
        uA = __shfl_xor_sync(0xffffffffu, uA, 16);
        uB = __shfl_xor_sync(0xffffffffu, uB, 16);
        if (hi) { v[0] = uA; v[1] = uB; } else { v[2] = uA; v[3] = uB; }
    }
}

#define PREACT(v) { \
    _Pragma("unroll") for (int b = 0; b < NB; ++b) \
        (v)[b] = fmaf(sa, ftanh_(sc * (v)[b]), sb); }

#define REDUCE_PBUF(PB, dst) { \
    float4 s4 = make_float4(0.f, 0.f, 0.f, 0.f); \
    const float4* p4 = (const float4*)&pbuf[PB][q][0]; \
    _Pragma("unroll") for (int k = 0; k < 12; ++k) { \
        float4 v4 = p4[k]; \
        s4.x += v4.x; s4.y += v4.y; s4.z += v4.z; s4.w += v4.w; } \
    (dst) = (s4.x + s4.y) + (s4.z + s4.w) \
          + pbuf[PB][q][48] + pbuf[PB][q][49] + pbuf[PB][q][50] + blin; }

// ===== A (layer-2 + output) step; S compile-time slot, SP = 1-S =====
#define ASTEP(t, S, SP) { \
    SYNC448(BFULL0 + S);                               /* h1(t) ready; A-internal barrier */ \
    if (red_lane && (t) >= 1 && (t) <= T - 1) {        /* deferred out(t-1) */ \
        float sres; REDUCE_PBUF(SP, sres); \
        out[(b0 + q) * Ttot + ((t) - 1)] = sres; \
    } \
    unsigned long long a2[NB]; \
    _Pragma("unroll") for (int b = 0; b < NB; ++b) a2[b] = pack2(bs2, 0.f); \
    _Pragma("unroll") for (int kk = 0; kk < 13; ++kk) {            /* W_hh2 . h2(t-1) */ \
        _Pragma("unroll") for (int b = 0; b < NB; ++b) { \
            unsigned long long q0, q1; \
            lds128(q0, q1, hb[b] + H2OFF + (SP) * SLOT_B + kk * 16u); \
            ffma2(a2[b], w2h[2*kk],     q0); \
            ffma2(a2[b], w2h[2*kk + 1], q1); \
        } \
    } \
    _Pragma("unroll") for (int kk = 0; kk < 13; ++kk) {            /* W_ih2 . h1(t) */ \
        _Pragma("unroll") for (int b = 0; b < NB; ++b) { \
            unsigned long long p0, p1; \
            lds128(p0, p1, hb[b] + (S) * SLOT_B + kk * 16u); \
            ffma2(a2[b], w2i[2*kk],     p0); \
            ffma2(a2[b], w2i[2*kk + 1], p1); \
        } \
    } \
    float v[4]; \
    _Pragma("unroll") for (int b = 0; b < NB; ++b) v[b] = sum2(a2[b]); \
    PREACT(v) \
    transp4(v, lane); \
    { \
        float cg = v[1] * c2 + v[0] * v[2]; \
        c2 = cg; \
        float h2v = v[3] * ftanh_(cg); \
        if (act) { \
            hring[1][S][q][j] = h2v; \
            pbuf[S][q][j] = wl * h2v; \
        } \
    } \
    if ((t) >= T - 1) {                                /* immediate out(t) + x feedback */ \
        SYNCA(); \
        if (red_lane) { \
            float s2; REDUCE_PBUF(S, s2); \
            out[(b0 + q) * Ttot + (t)] = s2; \
            if ((t) <= Ttot - 2) xout[q] = s2; \
        } \
        if ((t) <= Ttot - 2) ARRIVE448(BXB); \
    } \
    if ((t) < Ttot - 2) ARRIVE448(BFREE0 + S);         /* slot S free for B-step t+2 */ \
}

// ===== B (layer-1) step; computes h1(t) =====
#define BSTEP(t, S, SP) { \
    SYNC448(BFREE0 + S);                               /* slot free; B-internal barrier */ \
    float xv[4]; \
    if ((t) >= T) { \
        SYNC448(BXB);                                  /* out(t-1) ready */ \
        _Pragma("unroll") for (int b = 0; b < NB; ++b) xv[b] = xout[b]; \
    } else { \
        _Pragma("unroll") for (int b = 0; b < NB; ++b) xv[b] = xslot[(t) & 3][b]; \
    } \
    unsigned long long a1[NB]; \
    _Pragma("unroll") for (int b = 0; b < NB; ++b) a1[b] = pack2(bs1, 0.f); \
    _Pragma("unroll") for (int kk = 0; kk < 13; ++kk) {            /* W_hh1 . h1(t-1) */ \
        _Pragma("unroll") for (int b = 0; b < NB; ++b) { \
            unsigned long long p0, p1; \
            lds128(p0, p1, hb[b] + (SP) * SLOT_B + kk * 16u); \
            ffma2(a1[b], w1p[2*kk],     p0); \
            ffma2(a1[b], w1p[2*kk + 1], p1); \
        } \
    } \
    float v[4]; \
    _Pragma("unroll") for (int b = 0; b < NB; ++b) \
        v[b] = fmaf(xv[b], wi1, sum2(a1[b])); \
    PREACT(v) \
    transp4(v, lane); \
    { \
        float cg = v[1] * c1 + v[0] * v[2]; \
        c1 = cg; \
        float h1 = v[3] * ftanh_(cg); \
        if (act) hring[0][S][q][j] = h1; \
    } \
    if (pre_lane) { \
        if ((t) + 2 < T) xslot[((t) + 2) & 3][q] = xpre; \
        if ((t) + 3 < T) xpre = input[(b0 + q) * T + (t) + 3]; \
    } \
    ARRIVE448(BFULL0 + S);                             /* h1(t) published */ \
}

__global__ void __launch_bounds__(NTH, 1)
lstm2_kernel(const float* __restrict__ input,
             const float* __restrict__ W_ih1, const float* __restrict__ W_hh1,
             const float* __restrict__ b_ih1, const float* __restrict__ b_hh1,
             const float* __restrict__ W_ih2, const float* __restrict__ W_hh2,
             const float* __restrict__ b_ih2, const float* __restrict__ b_hh2,
             const float* __restrict__ W_lin, const float* __restrict__ b_lin,
             float* __restrict__ out, int T, int Ttot)
{
    __shared__ __align__(16) float hring[2][2][NB][RSTR];  // [h1/h2][slot][b][k]
    __shared__ __align__(16) float pbuf[2][NB][68];
    __shared__ float xslot[4][NB];
    __shared__ float xout[NB];

    const int  tid  = threadIdx.x;
    const int  lane = tid & 31;
    const int  wid  = tid >> 5;
    const bool isA  = (wid < 7);
    const int  wig  = isA ? wid : (wid - 7);
    const int  jloc = lane & 7;
    const int  q    = (lane >> 3) & 3;       // gate for dots; batch for updates
    const int  j    = wig * 8 + jloc;
    const bool act  = (j < Hh);
    const int  b0   = blockIdx.x * NB;
    const int  row  = q * Hh + (act ? j : 0);

    const bool red_lane = isA  && (wig == 6) && (jloc == 4);   // A: out reduce, batch q
    const bool pre_lane = !isA && (wig == 6) && (jloc == 3);   // B: x prefetch, batch q

    for (int i = tid; i < 2 * 2 * NB * RSTR; i += NTH) (&hring[0][0][0][0])[i] = 0.f;
    for (int i = tid; i < 2 * NB * 68; i += NTH) (&pbuf[0][0][0])[i] = 0.f;
    if (tid < NB) {
        xslot[0][tid] = input[(b0 + tid) * T];
        xslot[1][tid] = input[(b0 + tid) * T + 1];
        xout[tid] = 0.f;
    }

    // PREACT constants for MY gate (q==2 is the tanh 'g' gate)
    const float sc = (q == 2) ? 1.0f : 0.5f;
    const float sa = sc;
    const float sb = (q == 2) ? 0.0f : 0.5f;
    const float blin = b_lin[0];

    unsigned hb[NB];
    #pragma unroll
    for (int b = 0; b < NB; ++b)
        hb[b] = (unsigned)__cvta_generic_to_shared(&hring[0][0][b][0]);

    __syncthreads();                         // init visible to both groups

    if (isA) {
        // ---- layer-2 weights in registers ----
        unsigned long long w2i[26], w2h[26];
        {
            const float* ri = W_ih2 + row * Hh;
            const float* rh = W_hh2 + row * Hh;
            #pragma unroll
            for (int k = 0; k < 26; ++k) {
                int k0 = 2*k, k1 = 2*k + 1;
                float a = (act && k0 < 51) ? ri[k0] : 0.f;
                float b = (act && k1 < 51) ? ri[k1] : 0.f;
                w2i[k] = pack2(a, b);
                float c = (act && k0 < 51) ? rh[k0] : 0.f;
                float d = (act && k1 < 51) ? rh[k1] : 0.f;
                w2h[k] = pack2(c, d);
            }
        }
        const float bs2 = act ? (b_ih2[row] + b_hh2[row]) : 0.f;
        const float wl  = act ? W_lin[j] : 0.f;
        float c2 = 0.f;

        ARRIVE448(BFREE0);                   // pre-arm both FREE slots
        ARRIVE448(BFREE1);

        for (int t = 0; t < Ttot; t += 2) {
            ASTEP(t,     0, 1)
            ASTEP(t + 1, 1, 0)
        }
    } else {
        // ---- layer-1 weights in registers ----
        unsigned long long w1p[26];
        {
            const float* r1 = W_hh1 + row * Hh;
            #pragma unroll
            for (int k = 0; k < 26; ++k) {
                int k0 = 2*k, k1 = 2*k + 1;
                float a = (act && k0 < 51) ? r1[k0] : 0.f;
                float b = (act && k1 < 51) ? r1[k1] : 0.f;
                w1p[k] = pack2(a, b);
            }
        }
        const float wi1 = act ? W_ih1[row] : 0.f;
        const float bs1 = act ? (b_ih1[row] + b_hh1[row]) : 0.f;
        float c1 = 0.f, xpre = 0.f;
        if (pre_lane && 2 < T) xpre = input[(b0 + q) * T + 2];

        for (int t = 0; t < Ttot; t += 2) {
            BSTEP(t,     0, 1)
            BSTEP(t + 1, 1, 0)
        }
    }
}

extern "C" void kernel_launch(void* const* d_in, const int* in_sizes, int n_in,
                              void* d_out, int out_size) {
    const float* input = (const float*)d_in[0];
    const float* W_ih1 = (const float*)d_in[1];
    const float* W_hh1 = (const float*)d_in[2];
    const float* b_ih1 = (const float*)d_in[3];
    const float* b_hh1 = (const float*)d_in[4];
    const float* W_ih2 = (const float*)d_in[5];
    const float* W_hh2 = (const float*)d_in[6];
    const float* b_ih2 = (const float*)d_in[7];
    const float* b_hh2 = (const float*)d_in[8];
    const float* W_lin = (const float*)d_in[9];
    const float* b_lin = (const float*)d_in[10];

    const int T    = in_sizes[0] / BTOT;   // 1024
    const int Ttot = out_size    / BTOT;   // 1088 (even)

    lstm2_kernel<<<BTOT / NB, NTH>>>(input, W_ih1, W_hh1, b_ih1, b_hh1,
                                     W_ih2, W_hh2, b_ih2, b_hh2,
                                     W_lin, b_lin,
                                     (float*)d_out, T, Ttot);
}